// round 12
// baseline (speedup 1.0000x reference)
#include <cuda_runtime.h>
#include <cuda_bf16.h>
#include <cstdint>

#define NNODES 100000
#define MHE    200000
#define NEDGE  2000000

#define SA 136              // padded row stride (bf16 elems): 272 bytes

// ---------------- scratch (static __device__) ----------------
static __device__ __align__(16) float4 g_she[2 * MHE * 4];
static __device__ __align__(16) float4 g_agg[2 * NNODES * 4];
static __device__ __align__(16) float  g_bdeg[2 * MHE];
static __device__ __align__(16) float  g_ddeg[2 * NNODES];
static __device__ __align__(16) float  g_Wcm[2048];              // [32][64]
static __device__ __align__(16) float  g_bprime[64];
static __device__ __align__(16) __nv_bfloat16 g_Bh[256 * SA];    // B hi, padded row-major [n][k]
static __device__ __align__(16) __nv_bfloat16 g_Bl[256 * SA];    // B lo
static __device__ __align__(16) float  g_br[64], g_bz[64], g_bni[64], g_bnh[64];

// smem byte offsets for k_gru (64-row A tiles, double buffered)
#define A0_HI_OFF  0                 // 64*272 = 17408
#define A0_LO_OFF  17408
#define A1_HI_OFF  34816
#define A1_LO_OFF  52224
#define B_HI_OFF   69632             // 256*272 = 69632
#define B_LO_OFF   139264
#define WCM_OFF    208896            // 8192
#define BR_OFF     217088
#define BZ_OFF     217344
#define BNI_OFF    217600
#define BNH_OFF    217856
#define BP_OFF     218112
#define WO_OFF     218368            // 768
#define PRED0_OFF  219136            // 64*3*4 = 768
#define PRED1_OFF  219904            // 768
#define SMEM_TOTAL 220672

// ---------------- helpers ----------------
__device__ __forceinline__ void red4(float4* addr, float4 v) {
    asm volatile("red.global.add.v4.f32 [%0], {%1,%2,%3,%4};"
                 :: "l"(addr), "f"(v.x), "f"(v.y), "f"(v.z), "f"(v.w) : "memory");
}
__device__ __forceinline__ void red1(float* addr, float v) {
    asm volatile("red.global.add.f32 [%0], %1;" :: "l"(addr), "f"(v) : "memory");
}
__device__ __forceinline__ float sigf(float x) {
    float e = __expf(-x);
    return __fdividef(1.f, 1.f + e);
}
__device__ __forceinline__ float tanhfast(float x) {
    float e = __expf(-2.f * x);
    return __fdividef(1.f - e, 1.f + e);
}
__device__ __forceinline__ uint32_t smem_u32(const void* p) {
    uint32_t a;
    asm("{ .reg .u64 t; cvta.to.shared.u64 t, %1; cvt.u32.u64 %0, t; }" : "=r"(a) : "l"(p));
    return a;
}
__device__ __forceinline__ void ldsm4(uint32_t& r0, uint32_t& r1, uint32_t& r2, uint32_t& r3,
                                      uint32_t addr) {
    asm volatile("ldmatrix.sync.aligned.m8n8.x4.shared.b16 {%0,%1,%2,%3}, [%4];"
                 : "=r"(r0), "=r"(r1), "=r"(r2), "=r"(r3) : "r"(addr));
}
__device__ __forceinline__ void ldsm2(uint32_t& r0, uint32_t& r1, uint32_t addr) {
    asm volatile("ldmatrix.sync.aligned.m8n8.x2.shared.b16 {%0,%1}, [%2];"
                 : "=r"(r0), "=r"(r1) : "r"(addr));
}
__device__ __forceinline__ void mma16816(float* c, uint32_t a0, uint32_t a1, uint32_t a2,
                                         uint32_t a3, uint32_t b0, uint32_t b1) {
    asm volatile("mma.sync.aligned.m16n8k16.row.col.f32.bf16.bf16.f32 "
                 "{%0,%1,%2,%3}, {%4,%5,%6,%7}, {%8,%9}, {%0,%1,%2,%3};"
                 : "+f"(c[0]), "+f"(c[1]), "+f"(c[2]), "+f"(c[3])
                 : "r"(a0), "r"(a1), "r"(a2), "r"(a3), "r"(b0), "r"(b1));
}
// split 16 fp32 values into bf16 hi/lo packed pairs (8 u32 each)
__device__ __forceinline__ void split16(const float* v, uint32_t* hi, uint32_t* lo) {
#pragma unroll
    for (int j = 0; j < 8; j++) {
        float a0 = v[2 * j], a1 = v[2 * j + 1];
        __nv_bfloat16 h0 = __float2bfloat16(a0);
        __nv_bfloat16 h1 = __float2bfloat16(a1);
        __nv_bfloat16 l0 = __float2bfloat16(a0 - __bfloat162float(h0));
        __nv_bfloat16 l1 = __float2bfloat16(a1 - __bfloat162float(h1));
        hi[j] = (uint32_t)__bfloat16_as_ushort(h0) | ((uint32_t)__bfloat16_as_ushort(h1) << 16);
        lo[j] = (uint32_t)__bfloat16_as_ushort(l0) | ((uint32_t)__bfloat16_as_ushort(l1) << 16);
    }
}

// ---------------- kernel 1: zero scratch + precompute all weights ----------------
__global__ void k_pre(const float* __restrict__ Wc, const float* __restrict__ bc,
                      const float* __restrict__ Wm, const float* __restrict__ bm,
                      const float* __restrict__ Wih, const float* __restrict__ Whh,
                      const float* __restrict__ bih, const float* __restrict__ bhh) {
    int i = blockIdx.x * 256 + threadIdx.x;
    float4 z = make_float4(0.f, 0.f, 0.f, 0.f);
    if (i < 1600000) { g_she[i] = z; return; }
    int j = i - 1600000;
    if (j < 800000) { g_agg[j] = z; return; }
    int k = i - 2400000;
    if (k >= 0 && k < 100000) { ((float4*)g_bdeg)[k] = z; return; }
    int l = i - 2500000;
    if (l >= 0 && l < 50000) { ((float4*)g_ddeg)[l] = z; return; }
    int m = i - 2550000;
    if (m >= 0 && m < 2112) {
        if (m < 2048) {
            int t = m >> 10, rem = m & 1023, ii = rem >> 6, jj = rem & 63;
            float acc = 0.f;
            for (int kk = 0; kk < 64; kk++)
                acc += Wc[(t * 16 + ii) * 64 + kk] * Wm[(t * 64 + kk) * 64 + jj];
            g_Wcm[m] = acc;
        } else {
            int jj = m - 2048;
            float acc = bm[jj];
            for (int t = 0; t < 2; t++)
                for (int kk = 0; kk < 64; kk++)
                    acc += bc[t * 64 + kk] * Wm[(t * 64 + kk) * 64 + jj];
            g_bprime[jj] = acc;
        }
        return;
    }
    int p = i - 2552112;
    if (p >= 0 && p < 32768) {
        // B[n][k]: n 0-63: r | 64-127: z | 128-191: i_n (H only) | 192-255: h_n (hprev only)
        int n = p >> 7, kk = p & 127;
        float w = 0.f;
        if (kk < 64) {
            if (n < 192) w = Wih[n * 64 + kk];
        } else {
            if (n < 128) w = Whh[n * 64 + (kk - 64)];
            else if (n >= 192) w = Whh[(n - 64) * 64 + (kk - 64)];
        }
        __nv_bfloat16 hi = __float2bfloat16(w);
        __nv_bfloat16 lo = __float2bfloat16(w - __bfloat162float(hi));
        g_Bh[n * SA + kk] = hi;
        g_Bl[n * SA + kk] = lo;
        if (p < 64) {
            g_br[p]  = bih[p] + bhh[p];
            g_bz[p]  = bih[64 + p] + bhh[64 + p];
            g_bni[p] = bih[128 + p];
            g_bnh[p] = bhh[128 + p];
        }
    }
}

// ---------------- kernel 2: scatter x -> hyperedges + degree counts (4 lanes/edge) ----------------
__global__ void k_scat1(const int* __restrict__ en, const int* __restrict__ eh,
                        const int* __restrict__ ea, const float4* __restrict__ x4) {
    int gid = blockIdx.x * 256 + threadIdx.x;
    int e = gid >> 2;
    if (e >= NEDGE) return;
    int sub = gid & 3;
    int node = __ldg(en + e), he = __ldg(eh + e), t = __ldg(ea + e);
    float4 v = x4[node * 4 + sub];
    red4(&g_she[(t * MHE + he) * 4 + sub], v);
    if (sub == 0) red1(&g_bdeg[t * MHE + he], 1.f);
    else if (sub == 1) red1(&g_ddeg[t * NNODES + node], 1.f);
}

// ---------------- kernel 3: hyperedges -> nodes (4 lanes/edge, Binv on the fly) ----------------
__global__ void k_scat2(const int* __restrict__ en, const int* __restrict__ eh,
                        const int* __restrict__ ea) {
    int gid = blockIdx.x * 256 + threadIdx.x;
    int e = gid >> 2;
    if (e >= NEDGE) return;
    int sub = gid & 3;
    int node = __ldg(en + e), he = __ldg(eh + e), t = __ldg(ea + e);
    float c = __ldg(&g_bdeg[t * MHE + he]);   // >= 1 for this edge's own key
    float bi = 1.0f / c;
    float4 v = g_she[(t * MHE + he) * 4 + sub];
    v.x *= bi; v.y *= bi; v.z *= bi; v.w *= bi;
    red4(&g_agg[(t * NNODES + node) * 4 + sub], v);
}

// ---------------- kernel 4: persistent pipelined HMMA mix+GRU+pred ----------------
// 148 CTAs x 256 threads (8 warps). 64-row node tiles, A double-buffered.
// Per iteration: GEMM(n) -> epilogue(n) -> stage-A(n+1) -> sync -> pred flush(n).
// Warp tile = 16 rows x 128 interleaved gate-cols; gate-aware K-stepping (288 HMMA/warp/tile).
__global__ __launch_bounds__(256, 1) void k_gru(const float* __restrict__ hprev,
                                                const float* __restrict__ Wout,
                                                const float* __restrict__ bout,
                                                float* __restrict__ out, int Nn) {
    extern __shared__ char smem[];
    const uint32_t sbase = smem_u32(smem);
    const int tid = threadIdx.x;
    const int wid = tid >> 5;
    const int lane = tid & 31;

    // ---- stage constants once per CTA ----
    {
        const uint4* bh = reinterpret_cast<const uint4*>(g_Bh);
        const uint4* bl = reinterpret_cast<const uint4*>(g_Bl);
        uint4* sbh = reinterpret_cast<uint4*>(smem + B_HI_OFF);
        uint4* sbl = reinterpret_cast<uint4*>(smem + B_LO_OFF);
        for (int i = tid; i < 4352; i += 256) { sbh[i] = bh[i]; sbl[i] = bl[i]; }
        float4* swc = reinterpret_cast<float4*>(smem + WCM_OFF);
        const float4* gwc = reinterpret_cast<const float4*>(g_Wcm);
        for (int i = tid; i < 512; i += 256) swc[i] = gwc[i];
        if (tid < 64) {
            ((float*)(smem + BR_OFF))[tid]  = g_br[tid];
            ((float*)(smem + BZ_OFF))[tid]  = g_bz[tid];
            ((float*)(smem + BNI_OFF))[tid] = g_bni[tid];
            ((float*)(smem + BNH_OFF))[tid] = g_bnh[tid];
            ((float*)(smem + BP_OFF))[tid]  = g_bprime[tid];
        }
        if (tid < 192) {
            ((float*)(smem + WO_OFF))[tid] = Wout[(tid / 3) * 64 + (tid % 3)];
            ((float*)(smem + PRED0_OFF))[tid] = 0.f;
            ((float*)(smem + PRED1_OFF))[tid] = 0.f;
        }
    }
    __syncthreads();

    const float* f_br  = (const float*)(smem + BR_OFF);
    const float* f_bz  = (const float*)(smem + BZ_OFF);
    const float* f_bni = (const float*)(smem + BNI_OFF);
    const float* f_bnh = (const float*)(smem + BNH_OFF);
    const float* f_bp  = (const float*)(smem + BP_OFF);
    const float* f_wcm = (const float*)(smem + WCM_OFF);
    const float* f_wo  = (const float*)(smem + WO_OFF);
    const float bo0 = __ldg(bout + 0), bo1 = __ldg(bout + 1), bo2 = __ldg(bout + 2);

    // stage-A mapping: 4 threads per row, 16 cols each
    const int arow = tid >> 2;          // 0..63
    const int aj0  = (tid & 3) * 16;

    // GEMM mapping: warp = 16-row stripe x 128 interleaved gate-cols
    const int rw   = (wid >> 1) * 16;   // stripe base (0,16,32,48)
    const int ch   = wid & 1;           // col half within each gate (0: j 0-31, 1: j 32-63)
    const int g    = lane >> 2;
    const int tid4 = lane & 3;
    const uint32_t a_row_byte  = (uint32_t)(rw + (lane & 15)) * (SA * 2) + (uint32_t)(lane >> 4) * 16;
    const uint32_t b_lane_byte = (uint32_t)(lane & 7) * (SA * 2) + (uint32_t)((lane >> 3) & 1) * 16;

    const int ntiles = (Nn + 63) >> 6;

    // ---- stage-A lambda ----
    auto stage_a = [&](int t2, int bufsel) {
        const int gn = t2 * 64 + arow;
        const bool valid = gn < Nn;
        float a[32];
        if (valid) {
            float c0 = __ldg(&g_ddeg[gn]), c1 = __ldg(&g_ddeg[NNODES + gn]);
            float d0 = (c0 > 0.f) ? 1.f / c0 : 0.f;
            float d1 = (c1 > 0.f) ? 1.f / c1 : 0.f;
#pragma unroll
            for (int q = 0; q < 4; q++) {
                float4 v = __ldg(&g_agg[(size_t)gn * 4 + q]);
                a[q * 4 + 0] = v.x * d0; a[q * 4 + 1] = v.y * d0;
                a[q * 4 + 2] = v.z * d0; a[q * 4 + 3] = v.w * d0;
                float4 w = __ldg(&g_agg[(size_t)(NNODES + gn) * 4 + q]);
                a[16 + q * 4 + 0] = w.x * d1; a[16 + q * 4 + 1] = w.y * d1;
                a[16 + q * 4 + 2] = w.z * d1; a[16 + q * 4 + 3] = w.w * d1;
            }
        } else {
#pragma unroll
            for (int q = 0; q < 32; q++) a[q] = 0.f;
        }
        float mx[16];
#pragma unroll
        for (int s = 0; s < 16; s++) mx[s] = f_bp[aj0 + s];
#pragma unroll
        for (int i2 = 0; i2 < 32; i2++) {
            float av = a[i2];
            const float* w = f_wcm + i2 * 64 + aj0;
#pragma unroll
            for (int s = 0; s < 16; s++) mx[s] += av * w[s];
        }
#pragma unroll
        for (int s = 0; s < 16; s++) mx[s] = fmaxf(mx[s], 0.f);
        uint32_t hi[8], lo[8];
        split16(mx, hi, lo);
        const int hbase = bufsel ? A1_HI_OFF : A0_HI_OFF;
        {
            uint32_t rb = (uint32_t)arow * (SA * 2) + (uint32_t)aj0 * 2;
            uint4* dh = (uint4*)(smem + hbase + rb);
            uint4* dl = (uint4*)(smem + hbase + 17408 + rb);
            dh[0] = ((uint4*)hi)[0]; dh[1] = ((uint4*)hi)[1];
            dl[0] = ((uint4*)lo)[0]; dl[1] = ((uint4*)lo)[1];
        }
        float hp[16];
        const float4* hq = (const float4*)(hprev + (size_t)gn * 64 + aj0);
#pragma unroll
        for (int q = 0; q < 4; q++) {
            float4 v = valid ? __ldg(hq + q) : make_float4(0.f, 0.f, 0.f, 0.f);
            hp[q * 4 + 0] = v.x; hp[q * 4 + 1] = v.y;
            hp[q * 4 + 2] = v.z; hp[q * 4 + 3] = v.w;
        }
        split16(hp, hi, lo);
        {
            uint32_t rb = (uint32_t)arow * (SA * 2) + 128u + (uint32_t)aj0 * 2;
            uint4* dh = (uint4*)(smem + hbase + rb);
            uint4* dl = (uint4*)(smem + hbase + 17408 + rb);
            dh[0] = ((uint4*)hi)[0]; dh[1] = ((uint4*)hi)[1];
            dl[0] = ((uint4*)lo)[0]; dl[1] = ((uint4*)lo)[1];
        }
    };

    // prologue: fill buffer 0 with tile blockIdx.x
    stage_a(blockIdx.x, 0);
    __syncthreads();

    int ti = 0;
    for (int tile = blockIdx.x; tile < ntiles; tile += gridDim.x, ti++) {
        const int bufsel = ti & 1;
        const uint32_t abase_hi = sbase + (bufsel ? A1_HI_OFF : A0_HI_OFF);
        const uint32_t bbase_hi = sbase + B_HI_OFF + b_lane_byte + (uint32_t)(ch * 32) * (SA * 2);
        const int tbase = tile * 64;

        // ============ GEMM: 16 rows x 128 interleaved cols, gate-aware ============
        // acc layout: r: [0..15], z: [16..31], i: [32..47], h: [48..63]
        float acc[64];
#pragma unroll
        for (int s = 0; s < 64; s++) acc[s] = 0.f;

#pragma unroll
        for (int ks = 0; ks < 8; ks++) {
            uint32_t ah0, ah1, ah2, ah3, al0, al1, al2, al3;
            uint32_t aaddr = abase_hi + a_row_byte + (uint32_t)ks * 32;
            ldsm4(ah0, ah1, ah2, ah3, aaddr);
            ldsm4(al0, al1, al2, al3, aaddr + 17408);
            // r, z gates: all k
#pragma unroll
            for (int G = 0; G < 2; G++) {
#pragma unroll
                for (int nt = 0; nt < 4; nt++) {
                    uint32_t baddr = bbase_hi + (uint32_t)(G * 64 + nt * 8) * (SA * 2)
                                   + (uint32_t)ks * 32;
                    uint32_t bh0, bh1, bl0, bl1;
                    ldsm2(bh0, bh1, baddr);
                    ldsm2(bl0, bl1, baddr + 69632);
                    float* c = acc + G * 16 + nt * 4;
                    mma16816(c, ah0, ah1, ah2, ah3, bh0, bh1);
                    mma16816(c, ah0, ah1, ah2, ah3, bl0, bl1);
                    mma16816(c, al0, al1, al2, al3, bh0, bh1);
                }
            }
            // i_n (ks<4, k<64) or h_n (ks>=4, k>=64)
            {
                const int G2 = (ks < 4) ? 2 : 3;
                const int ab = (ks < 4) ? 32 : 48;
#pragma unroll
                for (int nt = 0; nt < 4; nt++) {
                    uint32_t baddr = bbase_hi + (uint32_t)(G2 * 64 + nt * 8) * (SA * 2)
                                   + (uint32_t)ks * 32;
                    uint32_t bh0, bh1, bl0, bl1;
                    ldsm2(bh0, bh1, baddr);
                    ldsm2(bl0, bl1, baddr + 69632);
                    float* c = acc + ab + nt * 4;
                    mma16816(c, ah0, ah1, ah2, ah3, bh0, bh1);
                    mma16816(c, ah0, ah1, ah2, ah3, bl0, bl1);
                    mma16816(c, al0, al1, al2, al3, bh0, bh1);
                }
            }
        }

        // ============ epilogue: GRU combine + store + pred partials ============
        float* pred_sm = (float*)(smem + (bufsel ? PRED1_OFF : PRED0_OFF));
#pragma unroll
        for (int rsel = 0; rsel < 2; rsel++) {
            const int lrow = rw + g + rsel * 8;
            const int gn = tbase + lrow;
            const bool ev = gn < Nn;
            const int ci = rsel * 2;
            float p0 = 0.f, p1 = 0.f, p2 = 0.f;
#pragma unroll
            for (int nt = 0; nt < 4; nt++) {
                const int jc0 = ch * 32 + nt * 8 + tid4 * 2;
                float2 hp = ev ? __ldg((const float2*)(hprev + (size_t)gn * 64 + jc0))
                               : make_float2(0.f, 0.f);
                float res[2];
#pragma unroll
                for (int s = 0; s < 2; s++) {
                    const int jc = jc0 + s;
                    float rv = acc[nt * 4 + ci + s]      + f_br[jc];
                    float zv = acc[16 + nt * 4 + ci + s] + f_bz[jc];
                    float iv = acc[32 + nt * 4 + ci + s] + f_bni[jc];
                    float hv = acc[48 + nt * 4 + ci + s] + f_bnh[jc];
                    float r = sigf(rv);
                    float z = sigf(zv);
                    float nn = tanhfast(iv + r * hv);
                    float hpv = s ? hp.y : hp.x;
                    res[s] = (1.f - z) * nn + z * hpv;
                    p0 += res[s] * f_wo[jc * 3 + 0];
                    p1 += res[s] * f_wo[jc * 3 + 1];
                    p2 += res[s] * f_wo[jc * 3 + 2];
                }
                if (ev) *(float2*)(out + (size_t)gn * 64 + jc0) = make_float2(res[0], res[1]);
            }
#pragma unroll
            for (int m2 = 1; m2 < 4; m2 <<= 1) {
                p0 += __shfl_xor_sync(0xffffffffu, p0, m2);
                p1 += __shfl_xor_sync(0xffffffffu, p1, m2);
                p2 += __shfl_xor_sync(0xffffffffu, p2, m2);
            }
            if (tid4 == 0) {
                atomicAdd(&pred_sm[lrow * 3 + 0], p0);
                atomicAdd(&pred_sm[lrow * 3 + 1], p1);
                atomicAdd(&pred_sm[lrow * 3 + 2], p2);
            }
        }

        // ============ stage A for next tile into the other buffer ============
        const int nxt = tile + gridDim.x;
        if (nxt < ntiles) stage_a(nxt, bufsel ^ 1);

        __syncthreads();   // all epilogue adds + stage-A writes complete

        // ============ pred flush for this tile (other threads run ahead) ============
        if (tid < 192) {
            const int r = tid / 3, c = tid - r * 3;
            const int gn = tbase + r;
            if (gn < Nn)
                out[(size_t)Nn * 64 + (size_t)gn * 3 + c] =
                    pred_sm[tid] + (c == 0 ? bo0 : (c == 1 ? bo1 : bo2));
            pred_sm[tid] = 0.f;
        }
    }
}

// ---------------- launch ----------------
extern "C" void kernel_launch(void* const* d_in, const int* in_sizes, int n_in,
                              void* d_out, int out_size) {
    const float* x     = (const float*)d_in[0];
    const float* hprev = (const float*)d_in[1];
    const int*   en    = (const int*)d_in[2];
    const int*   eh    = (const int*)d_in[3];
    const int*   ea    = (const int*)d_in[4];
    const float* Wconv = (const float*)d_in[5];
    const float* bconv = (const float*)d_in[6];
    const float* Wmix  = (const float*)d_in[7];
    const float* bmix  = (const float*)d_in[8];
    const float* Wih   = (const float*)d_in[9];
    const float* Whh   = (const float*)d_in[10];
    const float* bih   = (const float*)d_in[11];
    const float* bhh   = (const float*)d_in[12];
    const float* Wout  = (const float*)d_in[13];
    const float* bout  = (const float*)d_in[14];
    float* out = (float*)d_out;

    (void)in_sizes; (void)n_in; (void)out_size;

    k_pre<<<10098, 256>>>(Wconv, bconv, Wmix, bmix, Wih, Whh, bih, bhh);
    k_scat1<<<31250, 256>>>(en, eh, ea, (const float4*)x);
    k_scat2<<<31250, 256>>>(en, eh, ea);

    cudaFuncSetAttribute(k_gru, cudaFuncAttributeMaxDynamicSharedMemorySize, SMEM_TOTAL);
    k_gru<<<148, 256, SMEM_TOTAL>>>(hprev, Wout, bout, out, NNODES);
}

// round 15
// speedup vs baseline: 1.1719x; 1.1719x over previous
#include <cuda_runtime.h>
#include <cuda_bf16.h>
#include <cstdint>

#define NNODES 100000
#define MHE    200000
#define NEDGE  2000000

// ---------------- scratch (static __device__) ----------------
static __device__ __align__(16) float4 g_she[2 * MHE * 4];
static __device__ __align__(16) float4 g_agg[2 * NNODES * 4];
static __device__ __align__(16) float  g_bdeg[2 * MHE];
static __device__ __align__(16) float  g_ddeg[2 * NNODES];
static __device__ __align__(16) float  g_Wcm[2048];              // [32][64]
static __device__ __align__(16) float  g_bprime[64];
static __device__ __align__(16) uint32_t g_Bt[256 * 144];        // B tf32, fragment-packed
static __device__ __align__(16) float  g_br[64], g_bz[64], g_bni[64], g_bnh[64];

// smem byte offsets for k_gru
#define A_OFF      0                 // 8 blocks * 8224 = 65792
#define ABLK       8224
#define B_OFF      65792             // 256 rows * 576 = 147456
#define WCM_OFF    213248            // 8192
#define BR_OFF     221440
#define BZ_OFF     221696
#define BNI_OFF    221952
#define BNH_OFF    222208
#define BP_OFF     222464
#define WO_OFF     222720            // 768
#define SMEM_TOTAL 223488

// ---------------- helpers ----------------
__device__ __forceinline__ void red4(float4* addr, float4 v) {
    asm volatile("red.global.add.v4.f32 [%0], {%1,%2,%3,%4};"
                 :: "l"(addr), "f"(v.x), "f"(v.y), "f"(v.z), "f"(v.w) : "memory");
}
__device__ __forceinline__ void red1(float* addr, float v) {
    asm volatile("red.global.add.f32 [%0], %1;" :: "l"(addr), "f"(v) : "memory");
}
__device__ __forceinline__ float sigf(float x) {
    float e = __expf(-x);
    return __fdividef(1.f, 1.f + e);
}
__device__ __forceinline__ float tanhfast(float x) {
    float e = __expf(-2.f * x);
    return __fdividef(1.f - e, 1.f + e);
}
__device__ __forceinline__ uint32_t tf32r(float x) {
    uint32_t r; asm("cvt.rna.tf32.f32 %0, %1;" : "=r"(r) : "f"(x)); return r;
}
__device__ __forceinline__ void mmatf(float* c, uint32_t a0, uint32_t a1, uint32_t a2,
                                      uint32_t a3, uint32_t b0, uint32_t b1) {
    asm volatile("mma.sync.aligned.m16n8k8.row.col.f32.tf32.tf32.f32 "
                 "{%0,%1,%2,%3}, {%4,%5,%6,%7}, {%8,%9}, {%0,%1,%2,%3};"
                 : "+f"(c[0]), "+f"(c[1]), "+f"(c[2]), "+f"(c[3])
                 : "r"(a0), "r"(a1), "r"(a2), "r"(a3), "r"(b0), "r"(b1));
}

// ---------------- kernel 1: zero scratch + precompute all weights ----------------
__global__ void k_pre(const float* __restrict__ Wc, const float* __restrict__ bc,
                      const float* __restrict__ Wm, const float* __restrict__ bm,
                      const float* __restrict__ Wih, const float* __restrict__ Whh,
                      const float* __restrict__ bih, const float* __restrict__ bhh) {
    int i = blockIdx.x * 256 + threadIdx.x;
    float4 z = make_float4(0.f, 0.f, 0.f, 0.f);
    if (i < 1600000) { g_she[i] = z; return; }
    int j = i - 1600000;
    if (j < 800000) { g_agg[j] = z; return; }
    int k = i - 2400000;
    if (k >= 0 && k < 100000) { ((float4*)g_bdeg)[k] = z; return; }
    int l = i - 2500000;
    if (l >= 0 && l < 50000) { ((float4*)g_ddeg)[l] = z; return; }
    int m = i - 2550000;
    if (m >= 0 && m < 2112) {
        if (m < 2048) {
            int t = m >> 10, rem = m & 1023, ii = rem >> 6, jj = rem & 63;
            float acc = 0.f;
            for (int kk = 0; kk < 64; kk++)
                acc += Wc[(t * 16 + ii) * 64 + kk] * Wm[(t * 64 + kk) * 64 + jj];
            g_Wcm[m] = acc;
        } else {
            int jj = m - 2048;
            float acc = bm[jj];
            for (int t = 0; t < 2; t++)
                for (int kk = 0; kk < 64; kk++)
                    acc += bc[t * 64 + kk] * Wm[(t * 64 + kk) * 64 + jj];
            g_bprime[jj] = acc;
        }
        return;
    }
    int p = i - 2552112;
    if (p >= 0 && p < 32768) {
        // B[n][kg]: n 0-63: r | 64-127: z | 128-191: i_n (H only) | 192-255: h_n (hprev only)
        int n = p >> 7, kg = p & 127;
        float w = 0.f;
        if (kg < 64) {
            if (n < 192) w = Wih[n * 64 + kg];
        } else {
            if (n < 128) w = Whh[n * 64 + (kg - 64)];
            else if (n >= 192) w = Whh[(n - 64) * 64 + (kg - 64)];
        }
        int kl = kg & 15;
        // fragment-packed: row stride 144 u32; kb block of 16; chunk kl&3 holds {k0,k0+4,k0+8,k0+12}
        g_Bt[n * 144 + (kg >> 4) * 16 + (kl & 3) * 4 + (kl >> 2)] = tf32r(w);
        if (p < 64) {
            g_br[p]  = bih[p] + bhh[p];
            g_bz[p]  = bih[64 + p] + bhh[64 + p];
            g_bni[p] = bih[128 + p];
            g_bnh[p] = bhh[128 + p];
        }
    }
}

// ---------------- kernel 2: scatter x -> hyperedges + degree counts (4 lanes/edge) ----------------
__global__ void k_scat1(const int* __restrict__ en, const int* __restrict__ eh,
                        const int* __restrict__ ea, const float4* __restrict__ x4) {
    int gid = blockIdx.x * 256 + threadIdx.x;
    int e = gid >> 2;
    if (e >= NEDGE) return;
    int sub = gid & 3;
    int node = __ldg(en + e), he = __ldg(eh + e), t = __ldg(ea + e);
    float4 v = x4[node * 4 + sub];
    red4(&g_she[(t * MHE + he) * 4 + sub], v);
    if (sub == 0) red1(&g_bdeg[t * MHE + he], 1.f);
    else if (sub == 1) red1(&g_ddeg[t * NNODES + node], 1.f);
}

// ---------------- kernel 3: hyperedges -> nodes (4 lanes/edge, Binv on the fly) ----------------
__global__ void k_scat2(const int* __restrict__ en, const int* __restrict__ eh,
                        const int* __restrict__ ea) {
    int gid = blockIdx.x * 256 + threadIdx.x;
    int e = gid >> 2;
    if (e >= NEDGE) return;
    int sub = gid & 3;
    int node = __ldg(en + e), he = __ldg(eh + e), t = __ldg(ea + e);
    float c = __ldg(&g_bdeg[t * MHE + he]);   // >= 1 for this edge's own key
    float bi = 1.0f / c;
    float4 v = g_she[(t * MHE + he) * 4 + sub];
    v.x *= bi; v.y *= bi; v.z *= bi; v.w *= bi;
    red4(&g_agg[(t * NNODES + node) * 4 + sub], v);
}

// ---------------- kernel 4: persistent TF32-MMA mix+GRU+pred ----------------
// 148 CTAs x 256 threads (8 warps), warp tile = 16 rows x 256 gate-cols.
// Single-pass tf32 (no hi/lo split): 384 MMA + ~208 LDS.128 per warp per tile.
// Gate-aware K: i_n only kb 0-3, h_n only kb 4-7.
__global__ __launch_bounds__(256, 1) void k_gru(const float* __restrict__ hprev,
                                                const float* __restrict__ Wout,
                                                const float* __restrict__ bout,
                                                float* __restrict__ out, int Nn) {
    extern __shared__ char smem[];
    const int tid = threadIdx.x;
    const int wid = tid >> 5;
    const int lane = tid & 31;

    // ---- stage constants once per CTA ----
    {
        const uint4* bt = reinterpret_cast<const uint4*>(g_Bt);
        uint4* sbt = reinterpret_cast<uint4*>(smem + B_OFF);
        for (int i = tid; i < 9216; i += 256) sbt[i] = bt[i];
        float4* swc = reinterpret_cast<float4*>(smem + WCM_OFF);
        const float4* gwc = reinterpret_cast<const float4*>(g_Wcm);
        for (int i = tid; i < 512; i += 256) swc[i] = gwc[i];
        if (tid < 64) {
            ((float*)(smem + BR_OFF))[tid]  = g_br[tid];
            ((float*)(smem + BZ_OFF))[tid]  = g_bz[tid];
            ((float*)(smem + BNI_OFF))[tid] = g_bni[tid];
            ((float*)(smem + BNH_OFF))[tid] = g_bnh[tid];
            ((float*)(smem + BP_OFF))[tid]  = g_bprime[tid];
        }
        if (tid < 192) ((float*)(smem + WO_OFF))[tid] = Wout[(tid / 3) * 64 + (tid % 3)];
    }
    __syncthreads();

    const float* f_br  = (const float*)(smem + BR_OFF);
    const float* f_bz  = (const float*)(smem + BZ_OFF);
    const float* f_bni = (const float*)(smem + BNI_OFF);
    const float* f_bnh = (const float*)(smem + BNH_OFF);
    const float* f_bp  = (const float*)(smem + BP_OFF);
    const float* f_wcm = (const float*)(smem + WCM_OFF);
    const float* f_wo  = (const float*)(smem + WO_OFF);
    const float bo0 = __ldg(bout + 0), bo1 = __ldg(bout + 1), bo2 = __ldg(bout + 2);

    // stage-A mapping: 2 threads/row, 32 cols each
    const int row  = tid >> 1;          // 0..127
    const int j0m  = (tid & 1) * 32;

    // GEMM mapping
    const int wr0  = wid * 16;          // warp row stripe
    const int g    = lane >> 2;
    const int tid4 = lane & 3;
    const int rA   = wr0 + g;           // A fragment row (and rA+8)
    // A read: chunk swizzle c = (k0 + rA) & 3 (rA+8 gives same chunk)
    const uint32_t a_off1 = (uint32_t)rA * 64 + (uint32_t)(((tid4 + rA) & 3) * 16);
    // B read: lane row n-local = g, chunk = tid4
    const uint32_t b_off  = (uint32_t)g * 576 + (uint32_t)tid4 * 16;

    const int ntiles = (Nn + 127) >> 7;
    for (int tile = blockIdx.x; tile < ntiles; tile += gridDim.x) {
        const int nbase = tile << 7;

        // ============ stage A: build X_cat [128 rows][128 k] tf32, fragment-packed ============
        {
            const int gn = nbase + row;
            const bool valid = gn < Nn;
            float a[32];
            if (valid) {
                float c0 = __ldg(&g_ddeg[gn]), c1 = __ldg(&g_ddeg[NNODES + gn]);
                float d0 = (c0 > 0.f) ? 1.f / c0 : 0.f;
                float d1 = (c1 > 0.f) ? 1.f / c1 : 0.f;
#pragma unroll
                for (int q = 0; q < 4; q++) {
                    float4 v = __ldg(&g_agg[(size_t)gn * 4 + q]);
                    a[q * 4 + 0] = v.x * d0; a[q * 4 + 1] = v.y * d0;
                    a[q * 4 + 2] = v.z * d0; a[q * 4 + 3] = v.w * d0;
                    float4 w = __ldg(&g_agg[(size_t)(NNODES + gn) * 4 + q]);
                    a[16 + q * 4 + 0] = w.x * d1; a[16 + q * 4 + 1] = w.y * d1;
                    a[16 + q * 4 + 2] = w.z * d1; a[16 + q * 4 + 3] = w.w * d1;
                }
            } else {
#pragma unroll
                for (int q = 0; q < 32; q++) a[q] = 0.f;
            }
            float mx[32];
#pragma unroll
            for (int s = 0; s < 32; s++) mx[s] = f_bp[j0m + s];
#pragma unroll
            for (int i2 = 0; i2 < 32; i2++) {
                float av = a[i2];
                const float* w = f_wcm + i2 * 64 + j0m;
#pragma unroll
                for (int s = 0; s < 32; s++) mx[s] += av * w[s];
            }
            uint32_t tm[32];
#pragma unroll
            for (int s = 0; s < 32; s++) tm[s] = tf32r(fmaxf(mx[s], 0.f));
            // store mix (GEMM k = j0m..j0m+31 -> kb = j0m/16 + blk)
#pragma unroll
            for (int blk = 0; blk < 2; blk++) {
                const int kb = (j0m >> 4) + blk;
                char* base = smem + A_OFF + kb * ABLK + row * 64;
#pragma unroll
                for (int q = 0; q < 4; q++) {
                    const int c = (q + row) & 3;
                    uint4 val = make_uint4(tm[blk * 16 + q], tm[blk * 16 + q + 4],
                                           tm[blk * 16 + q + 8], tm[blk * 16 + q + 12]);
                    *(uint4*)(base + c * 16) = val;
                }
            }
            // h_prev (GEMM k = 64 + j0m .. +31 -> kb = 4 + j0m/16 + blk)
            uint32_t th[32];
            const float4* hq = (const float4*)(hprev + (size_t)gn * 64 + j0m);
#pragma unroll
            for (int q = 0; q < 8; q++) {
                float4 v = valid ? __ldg(hq + q) : make_float4(0.f, 0.f, 0.f, 0.f);
                th[q * 4 + 0] = tf32r(v.x); th[q * 4 + 1] = tf32r(v.y);
                th[q * 4 + 2] = tf32r(v.z); th[q * 4 + 3] = tf32r(v.w);
            }
#pragma unroll
            for (int blk = 0; blk < 2; blk++) {
                const int kb = 4 + (j0m >> 4) + blk;
                char* base = smem + A_OFF + kb * ABLK + row * 64;
#pragma unroll
                for (int q = 0; q < 4; q++) {
                    const int c = (q + row) & 3;
                    uint4 val = make_uint4(th[blk * 16 + q], th[blk * 16 + q + 4],
                                           th[blk * 16 + q + 8], th[blk * 16 + q + 12]);
                    *(uint4*)(base + c * 16) = val;
                }
            }
        }
        __syncthreads();

        // ============ GEMM: D[128][256] = Xcat @ B^T, single-pass tf32 ============
        // acc: r [0..31], z [32..63], i [64..95], h [96..127]
        float acc[128];
#pragma unroll
        for (int s = 0; s < 128; s++) acc[s] = 0.f;

#pragma unroll
        for (int kb = 0; kb < 8; kb++) {
            const char* ab = smem + A_OFF + kb * ABLK;
            uint4 fr  = *(const uint4*)(ab + a_off1);
            uint4 fr8 = *(const uint4*)(ab + a_off1 + 512);
            const char* bb = smem + B_OFF + b_off + kb * 64;
            // r, z gates: all kb
#pragma unroll
            for (int G = 0; G < 2; G++) {
#pragma unroll
                for (int nt = 0; nt < 8; nt++) {
                    uint4 gB = *(const uint4*)(bb + (size_t)(G * 64 + nt * 8) * 576);
                    float* c = acc + G * 32 + nt * 4;
                    mmatf(c, fr.x, fr8.x, fr.y, fr8.y, gB.x, gB.y);
                    mmatf(c, fr.z, fr8.z, fr.w, fr8.w, gB.z, gB.w);
                }
            }
            // i_n (kb<4) or h_n (kb>=4)
            {
                const int nb = (kb < 4) ? 128 : 192;
                float* cb = acc + ((kb < 4) ? 64 : 96);
#pragma unroll
                for (int nt = 0; nt < 8; nt++) {
                    uint4 gB = *(const uint4*)(bb + (size_t)(nb + nt * 8) * 576);
                    float* c = cb + nt * 4;
                    mmatf(c, fr.x, fr8.x, fr.y, fr8.y, gB.x, gB.y);
                    mmatf(c, fr.z, fr8.z, fr.w, fr8.w, gB.z, gB.w);
                }
            }
        }

        // ============ epilogue: GRU combine + store + fused pred ============
#pragma unroll
        for (int rsel = 0; rsel < 2; rsel++) {
            const int lrow = wr0 + g + rsel * 8;
            const int gn = nbase + lrow;
            const bool ev = gn < Nn;
            const int ci = rsel * 2;        // c0,c1 vs c2,c3
            float p0 = 0.f, p1 = 0.f, p2 = 0.f;
#pragma unroll
            for (int nt = 0; nt < 8; nt++) {
                const int jj = nt * 8 + tid4 * 2;
                float2 hp = ev ? __ldg((const float2*)(hprev + (size_t)gn * 64 + jj))
                               : make_float2(0.f, 0.f);
                float res[2];
#pragma unroll
                for (int s = 0; s < 2; s++) {
                    int jc = jj + s;
                    float rv = acc[nt * 4 + ci + s]       + f_br[jc];
                    float zv = acc[32 + nt * 4 + ci + s]  + f_bz[jc];
                    float iv = acc[64 + nt * 4 + ci + s]  + f_bni[jc];
                    float hv = acc[96 + nt * 4 + ci + s]  + f_bnh[jc];
                    float r = sigf(rv);
                    float z = sigf(zv);
                    float nn = tanhfast(iv + r * hv);
                    float hpv = s ? hp.y : hp.x;
                    res[s] = (1.f - z) * nn + z * hpv;
                    p0 += res[s] * f_wo[jc * 3 + 0];
                    p1 += res[s] * f_wo[jc * 3 + 1];
                    p2 += res[s] * f_wo[jc * 3 + 2];
                }
                if (ev) *(float2*)(out + (size_t)gn * 64 + jj) = make_float2(res[0], res[1]);
            }
#pragma unroll
            for (int m2 = 1; m2 < 4; m2 <<= 1) {
                p0 += __shfl_xor_sync(0xffffffffu, p0, m2);
                p1 += __shfl_xor_sync(0xffffffffu, p1, m2);
                p2 += __shfl_xor_sync(0xffffffffu, p2, m2);
            }
            if (tid4 == 0 && ev) {
                float* pp = out + (size_t)Nn * 64 + (size_t)gn * 3;
                pp[0] = p0 + bo0; pp[1] = p1 + bo1; pp[2] = p2 + bo2;
            }
        }
        __syncthreads();   // A smem reuse next tile
    }
}

// ---------------- launch ----------------
extern "C" void kernel_launch(void* const* d_in, const int* in_sizes, int n_in,
                              void* d_out, int out_size) {
    const float* x     = (const float*)d_in[0];
    const float* hprev = (const float*)d_in[1];
    const int*   en    = (const int*)d_in[2];
    const int*   eh    = (const int*)d_in[3];
    const int*   ea    = (const int*)d_in[4];
    const float* Wconv = (const float*)d_in[5];
    const float* bconv = (const float*)d_in[6];
    const float* Wmix  = (const float*)d_in[7];
    const float* bmix  = (const float*)d_in[8];
    const float* Wih   = (const float*)d_in[9];
    const float* Whh   = (const float*)d_in[10];
    const float* bih   = (const float*)d_in[11];
    const float* bhh   = (const float*)d_in[12];
    const float* Wout  = (const float*)d_in[13];
    const float* bout  = (const float*)d_in[14];
    float* out = (float*)d_out;

    (void)in_sizes; (void)n_in; (void)out_size;

    k_pre<<<10098, 256>>>(Wconv, bconv, Wmix, bmix, Wih, Whh, bih, bhh);
    k_scat1<<<31250, 256>>>(en, eh, ea, (const float4*)x);
    k_scat2<<<31250, 256>>>(en, eh, ea);

    cudaFuncSetAttribute(k_gru, cudaFuncAttributeMaxDynamicSharedMemorySize, SMEM_TOTAL);
    k_gru<<<148, 256, SMEM_TOTAL>>>(hprev, Wout, bout, out, NNODES);
}

// round 16
// speedup vs baseline: 1.1844x; 1.0106x over previous
#include <cuda_runtime.h>
#include <cuda_bf16.h>
#include <cstdint>

#define NNODES 100000
#define MHE    200000
#define NEDGE  2000000

// ---------------- scratch (static __device__) ----------------
static __device__ __align__(16) float4 g_she[2 * MHE * 4];
static __device__ __align__(16) float4 g_agg[2 * NNODES * 4];
static __device__ __align__(16) float  g_bdeg[2 * MHE];
static __device__ __align__(16) float  g_ddeg[2 * NNODES];
static __device__ __align__(16) float  g_Wcm[2048];              // [32][64]
static __device__ __align__(16) float  g_bprime[64];
static __device__ __align__(16) uint32_t g_Bt[256 * 144];        // B tf32, fragment-packed
static __device__ __align__(16) float  g_br[64], g_bz[64], g_bni[64], g_bnh[64];

// smem byte offsets for k_gru
#define A_OFF      0                 // 8 blocks * 8224 = 65792
#define ABLK       8224
#define B_OFF      65792             // 256 rows * 576 = 147456
#define WCM_OFF    213248            // 8192
#define BR_OFF     221440
#define BZ_OFF     221696
#define BNI_OFF    221952
#define BNH_OFF    222208
#define BP_OFF     222464
#define WO_OFF     222720            // 768
#define SMEM_TOTAL 223488

// ---------------- helpers ----------------
__device__ __forceinline__ void red4(float4* addr, float4 v) {
    asm volatile("red.global.add.v4.f32 [%0], {%1,%2,%3,%4};"
                 :: "l"(addr), "f"(v.x), "f"(v.y), "f"(v.z), "f"(v.w) : "memory");
}
__device__ __forceinline__ void red1(float* addr, float v) {
    asm volatile("red.global.add.f32 [%0], %1;" :: "l"(addr), "f"(v) : "memory");
}
__device__ __forceinline__ float sigf(float x) {
    float e = __expf(-x);
    return __fdividef(1.f, 1.f + e);
}
__device__ __forceinline__ float tanhfast(float x) {
    float e = __expf(-2.f * x);
    return __fdividef(1.f - e, 1.f + e);
}
__device__ __forceinline__ uint32_t tf32r(float x) {
    uint32_t r; asm("cvt.rna.tf32.f32 %0, %1;" : "=r"(r) : "f"(x)); return r;
}
__device__ __forceinline__ void mmatf(float* c, uint32_t a0, uint32_t a1, uint32_t a2,
                                      uint32_t a3, uint32_t b0, uint32_t b1) {
    asm volatile("mma.sync.aligned.m16n8k8.row.col.f32.tf32.tf32.f32 "
                 "{%0,%1,%2,%3}, {%4,%5,%6,%7}, {%8,%9}, {%0,%1,%2,%3};"
                 : "+f"(c[0]), "+f"(c[1]), "+f"(c[2]), "+f"(c[3])
                 : "r"(a0), "r"(a1), "r"(a2), "r"(a3), "r"(b0), "r"(b1));
}

// ---------------- kernel 1: zero scratch + precompute all weights ----------------
__global__ void k_pre(const float* __restrict__ Wc, const float* __restrict__ bc,
                      const float* __restrict__ Wm, const float* __restrict__ bm,
                      const float* __restrict__ Wih, const float* __restrict__ Whh,
                      const float* __restrict__ bih, const float* __restrict__ bhh) {
    int i = blockIdx.x * 256 + threadIdx.x;
    float4 z = make_float4(0.f, 0.f, 0.f, 0.f);
    if (i < 1600000) { g_she[i] = z; return; }
    int j = i - 1600000;
    if (j < 800000) { g_agg[j] = z; return; }
    int k = i - 2400000;
    if (k >= 0 && k < 100000) { ((float4*)g_bdeg)[k] = z; return; }
    int l = i - 2500000;
    if (l >= 0 && l < 50000) { ((float4*)g_ddeg)[l] = z; return; }
    int m = i - 2550000;
    if (m >= 0 && m < 2112) {
        if (m < 2048) {
            int t = m >> 10, rem = m & 1023, ii = rem >> 6, jj = rem & 63;
            float acc = 0.f;
            for (int kk = 0; kk < 64; kk++)
                acc += Wc[(t * 16 + ii) * 64 + kk] * Wm[(t * 64 + kk) * 64 + jj];
            g_Wcm[m] = acc;
        } else {
            int jj = m - 2048;
            float acc = bm[jj];
            for (int t = 0; t < 2; t++)
                for (int kk = 0; kk < 64; kk++)
                    acc += bc[t * 64 + kk] * Wm[(t * 64 + kk) * 64 + jj];
            g_bprime[jj] = acc;
        }
        return;
    }
    int p = i - 2552112;
    if (p >= 0 && p < 32768) {
        // B[n][kg]: n 0-63: r | 64-127: z | 128-191: i_n (H only) | 192-255: h_n (hprev only)
        int n = p >> 7, kg = p & 127;
        float w = 0.f;
        if (kg < 64) {
            if (n < 192) w = Wih[n * 64 + kg];
        } else {
            if (n < 128) w = Whh[n * 64 + (kg - 64)];
            else if (n >= 192) w = Whh[(n - 64) * 64 + (kg - 64)];
        }
        int kl = kg & 15;
        // fragment-packed: row stride 144 u32; kb block of 16; chunk kl&3 holds {k0,k0+4,k0+8,k0+12}
        g_Bt[n * 144 + (kg >> 4) * 16 + (kl & 3) * 4 + (kl >> 2)] = tf32r(w);
        if (p < 64) {
            g_br[p]  = bih[p] + bhh[p];
            g_bz[p]  = bih[64 + p] + bhh[64 + p];
            g_bni[p] = bih[128 + p];
            g_bnh[p] = bhh[128 + p];
        }
    }
}

// ---------------- kernel 2: scatter x -> hyperedges + degree counts (4 lanes/edge) ----------------
__global__ void k_scat1(const int* __restrict__ en, const int* __restrict__ eh,
                        const int* __restrict__ ea, const float4* __restrict__ x4) {
    int gid = blockIdx.x * 256 + threadIdx.x;
    int e = gid >> 2;
    if (e >= NEDGE) return;
    int sub = gid & 3;
    int node = __ldg(en + e), he = __ldg(eh + e), t = __ldg(ea + e);
    float4 v = x4[node * 4 + sub];
    red4(&g_she[(t * MHE + he) * 4 + sub], v);
    if (sub == 0) red1(&g_bdeg[t * MHE + he], 1.f);
    else if (sub == 1) red1(&g_ddeg[t * NNODES + node], 1.f);
}

// ---------------- kernel 3: hyperedges -> nodes (4 lanes/edge, Binv on the fly) ----------------
__global__ void k_scat2(const int* __restrict__ en, const int* __restrict__ eh,
                        const int* __restrict__ ea) {
    int gid = blockIdx.x * 256 + threadIdx.x;
    int e = gid >> 2;
    if (e >= NEDGE) return;
    int sub = gid & 3;
    int node = __ldg(en + e), he = __ldg(eh + e), t = __ldg(ea + e);
    float c = __ldg(&g_bdeg[t * MHE + he]);   // >= 1 for this edge's own key
    float bi = 1.0f / c;
    float4 v = g_she[(t * MHE + he) * 4 + sub];
    v.x *= bi; v.y *= bi; v.z *= bi; v.w *= bi;
    red4(&g_agg[(t * NNODES + node) * 4 + sub], v);
}

// ---------------- kernel 4: persistent TF32-MMA mix+GRU+pred ----------------
// 148 CTAs x 256 threads (8 warps), warp tile = 16 rows x 256 gate-cols.
// Warp-private A rows: stage-A writer warp == GEMM reader warp, so the tile loop
// needs only __syncwarp() -> warps free-run and phases overlap across warps.
__global__ __launch_bounds__(256, 1) void k_gru(const float* __restrict__ hprev,
                                                const float* __restrict__ Wout,
                                                const float* __restrict__ bout,
                                                float* __restrict__ out, int Nn) {
    extern __shared__ char smem[];
    const int tid = threadIdx.x;
    const int wid = tid >> 5;
    const int lane = tid & 31;

    // ---- stage constants once per CTA ----
    {
        const uint4* bt = reinterpret_cast<const uint4*>(g_Bt);
        uint4* sbt = reinterpret_cast<uint4*>(smem + B_OFF);
        for (int i = tid; i < 9216; i += 256) sbt[i] = bt[i];
        float4* swc = reinterpret_cast<float4*>(smem + WCM_OFF);
        const float4* gwc = reinterpret_cast<const float4*>(g_Wcm);
        for (int i = tid; i < 512; i += 256) swc[i] = gwc[i];
        if (tid < 64) {
            ((float*)(smem + BR_OFF))[tid]  = g_br[tid];
            ((float*)(smem + BZ_OFF))[tid]  = g_bz[tid];
            ((float*)(smem + BNI_OFF))[tid] = g_bni[tid];
            ((float*)(smem + BNH_OFF))[tid] = g_bnh[tid];
            ((float*)(smem + BP_OFF))[tid]  = g_bprime[tid];
        }
        if (tid < 192) ((float*)(smem + WO_OFF))[tid] = Wout[(tid / 3) * 64 + (tid % 3)];
    }
    __syncthreads();

    const float* f_br  = (const float*)(smem + BR_OFF);
    const float* f_bz  = (const float*)(smem + BZ_OFF);
    const float* f_bni = (const float*)(smem + BNI_OFF);
    const float* f_bnh = (const float*)(smem + BNH_OFF);
    const float* f_bp  = (const float*)(smem + BP_OFF);
    const float* f_wcm = (const float*)(smem + WCM_OFF);
    const float* f_wo  = (const float*)(smem + WO_OFF);
    const float bo0 = __ldg(bout + 0), bo1 = __ldg(bout + 1), bo2 = __ldg(bout + 2);

    // stage-A mapping: 2 threads/row, 32 cols each (warp w covers rows 16w..16w+15)
    const int row  = tid >> 1;          // 0..127
    const int j0m  = (tid & 1) * 32;

    // GEMM mapping (warp-private stripe)
    const int wr0  = wid * 16;          // warp row stripe
    const int g    = lane >> 2;
    const int tid4 = lane & 3;
    const int rA   = wr0 + g;           // A fragment row (and rA+8)
    // A read: chunk swizzle c = (k0 + rA) & 3 (rA+8 gives same chunk)
    const uint32_t a_off1 = (uint32_t)rA * 64 + (uint32_t)(((tid4 + rA) & 3) * 16);
    // B read: lane row n-local = g, chunk = tid4
    const uint32_t b_off  = (uint32_t)g * 576 + (uint32_t)tid4 * 16;

    const int ntiles = (Nn + 127) >> 7;
    for (int tile = blockIdx.x; tile < ntiles; tile += gridDim.x) {
        const int nbase = tile << 7;

        // ============ stage A: build X_cat [128 rows][128 k] tf32, fragment-packed ============
        {
            const int gn = nbase + row;
            const bool valid = gn < Nn;
            float a[32];
            if (valid) {
                float c0 = __ldg(&g_ddeg[gn]), c1 = __ldg(&g_ddeg[NNODES + gn]);
                float d0 = (c0 > 0.f) ? 1.f / c0 : 0.f;
                float d1 = (c1 > 0.f) ? 1.f / c1 : 0.f;
#pragma unroll
                for (int q = 0; q < 4; q++) {
                    float4 v = __ldg(&g_agg[(size_t)gn * 4 + q]);
                    a[q * 4 + 0] = v.x * d0; a[q * 4 + 1] = v.y * d0;
                    a[q * 4 + 2] = v.z * d0; a[q * 4 + 3] = v.w * d0;
                    float4 w = __ldg(&g_agg[(size_t)(NNODES + gn) * 4 + q]);
                    a[16 + q * 4 + 0] = w.x * d1; a[16 + q * 4 + 1] = w.y * d1;
                    a[16 + q * 4 + 2] = w.z * d1; a[16 + q * 4 + 3] = w.w * d1;
                }
            } else {
#pragma unroll
                for (int q = 0; q < 32; q++) a[q] = 0.f;
            }
            float mx[32];
#pragma unroll
            for (int s = 0; s < 32; s++) mx[s] = f_bp[j0m + s];
#pragma unroll
            for (int i2 = 0; i2 < 32; i2++) {
                float av = a[i2];
                const float* w = f_wcm + i2 * 64 + j0m;
#pragma unroll
                for (int s = 0; s < 32; s++) mx[s] += av * w[s];
            }
            uint32_t tm[32];
#pragma unroll
            for (int s = 0; s < 32; s++) tm[s] = tf32r(fmaxf(mx[s], 0.f));
            // store mix (GEMM k = j0m..j0m+31 -> kb = j0m/16 + blk)
#pragma unroll
            for (int blk = 0; blk < 2; blk++) {
                const int kb = (j0m >> 4) + blk;
                char* base = smem + A_OFF + kb * ABLK + row * 64;
#pragma unroll
                for (int q = 0; q < 4; q++) {
                    const int c = (q + row) & 3;
                    uint4 val = make_uint4(tm[blk * 16 + q], tm[blk * 16 + q + 4],
                                           tm[blk * 16 + q + 8], tm[blk * 16 + q + 12]);
                    *(uint4*)(base + c * 16) = val;
                }
            }
            // h_prev (GEMM k = 64 + j0m .. +31 -> kb = 4 + j0m/16 + blk)
            uint32_t th[32];
            const float4* hq = (const float4*)(hprev + (size_t)gn * 64 + j0m);
#pragma unroll
            for (int q = 0; q < 8; q++) {
                float4 v = valid ? __ldg(hq + q) : make_float4(0.f, 0.f, 0.f, 0.f);
                th[q * 4 + 0] = tf32r(v.x); th[q * 4 + 1] = tf32r(v.y);
                th[q * 4 + 2] = tf32r(v.z); th[q * 4 + 3] = tf32r(v.w);
            }
#pragma unroll
            for (int blk = 0; blk < 2; blk++) {
                const int kb = 4 + (j0m >> 4) + blk;
                char* base = smem + A_OFF + kb * ABLK + row * 64;
#pragma unroll
                for (int q = 0; q < 4; q++) {
                    const int c = (q + row) & 3;
                    uint4 val = make_uint4(th[blk * 16 + q], th[blk * 16 + q + 4],
                                           th[blk * 16 + q + 8], th[blk * 16 + q + 12]);
                    *(uint4*)(base + c * 16) = val;
                }
            }
        }
        __syncwarp();   // A rows are warp-private: intra-warp ordering suffices

        // ============ GEMM: D[128][256] = Xcat @ B^T, single-pass tf32 ============
        // acc: r [0..31], z [32..63], i [64..95], h [96..127]
        float acc[128];
#pragma unroll
        for (int s = 0; s < 128; s++) acc[s] = 0.f;

#pragma unroll
        for (int kb = 0; kb < 8; kb++) {
            const char* ab = smem + A_OFF + kb * ABLK;
            uint4 fr  = *(const uint4*)(ab + a_off1);
            uint4 fr8 = *(const uint4*)(ab + a_off1 + 512);
            const char* bb = smem + B_OFF + b_off + kb * 64;
            // r, z gates: all kb
#pragma unroll
            for (int G = 0; G < 2; G++) {
#pragma unroll
                for (int nt = 0; nt < 8; nt++) {
                    uint4 gB = *(const uint4*)(bb + (size_t)(G * 64 + nt * 8) * 576);
                    float* c = acc + G * 32 + nt * 4;
                    mmatf(c, fr.x, fr8.x, fr.y, fr8.y, gB.x, gB.y);
                    mmatf(c, fr.z, fr8.z, fr.w, fr8.w, gB.z, gB.w);
                }
            }
            // i_n (kb<4) or h_n (kb>=4)
            {
                const int nb = (kb < 4) ? 128 : 192;
                float* cb = acc + ((kb < 4) ? 64 : 96);
#pragma unroll
                for (int nt = 0; nt < 8; nt++) {
                    uint4 gB = *(const uint4*)(bb + (size_t)(nb + nt * 8) * 576);
                    float* c = cb + nt * 4;
                    mmatf(c, fr.x, fr8.x, fr.y, fr8.y, gB.x, gB.y);
                    mmatf(c, fr.z, fr8.z, fr.w, fr8.w, gB.z, gB.w);
                }
            }
        }

        // ============ epilogue: GRU combine + store + fused pred ============
#pragma unroll
        for (int rsel = 0; rsel < 2; rsel++) {
            const int lrow = wr0 + g + rsel * 8;
            const int gn = nbase + lrow;
            const bool ev = gn < Nn;
            const int ci = rsel * 2;        // c0,c1 vs c2,c3
            float p0 = 0.f, p1 = 0.f, p2 = 0.f;
#pragma unroll
            for (int nt = 0; nt < 8; nt++) {
                const int jj = nt * 8 + tid4 * 2;
                float2 hp = ev ? __ldg((const float2*)(hprev + (size_t)gn * 64 + jj))
                               : make_float2(0.f, 0.f);
                float res[2];
#pragma unroll
                for (int s = 0; s < 2; s++) {
                    int jc = jj + s;
                    float rv = acc[nt * 4 + ci + s]       + f_br[jc];
                    float zv = acc[32 + nt * 4 + ci + s]  + f_bz[jc];
                    float iv = acc[64 + nt * 4 + ci + s]  + f_bni[jc];
                    float hv = acc[96 + nt * 4 + ci + s]  + f_bnh[jc];
                    float r = sigf(rv);
                    float z = sigf(zv);
                    float nn = tanhfast(iv + r * hv);
                    float hpv = s ? hp.y : hp.x;
                    res[s] = (1.f - z) * nn + z * hpv;
                    p0 += res[s] * f_wo[jc * 3 + 0];
                    p1 += res[s] * f_wo[jc * 3 + 1];
                    p2 += res[s] * f_wo[jc * 3 + 2];
                }
                if (ev) *(float2*)(out + (size_t)gn * 64 + jj) = make_float2(res[0], res[1]);
            }
#pragma unroll
            for (int m2 = 1; m2 < 4; m2 <<= 1) {
                p0 += __shfl_xor_sync(0xffffffffu, p0, m2);
                p1 += __shfl_xor_sync(0xffffffffu, p1, m2);
                p2 += __shfl_xor_sync(0xffffffffu, p2, m2);
            }
            if (tid4 == 0 && ev) {
                float* pp = out + (size_t)Nn * 64 + (size_t)gn * 3;
                pp[0] = p0 + bo0; pp[1] = p1 + bo1; pp[2] = p2 + bo2;
            }
        }
        __syncwarp();   // A smem reuse next tile (warp-private)
    }
}

// ---------------- launch ----------------
extern "C" void kernel_launch(void* const* d_in, const int* in_sizes, int n_in,
                              void* d_out, int out_size) {
    const float* x     = (const float*)d_in[0];
    const float* hprev = (const float*)d_in[1];
    const int*   en    = (const int*)d_in[2];
    const int*   eh    = (const int*)d_in[3];
    const int*   ea    = (const int*)d_in[4];
    const float* Wconv = (const float*)d_in[5];
    const float* bconv = (const float*)d_in[6];
    const float* Wmix  = (const float*)d_in[7];
    const float* bmix  = (const float*)d_in[8];
    const float* Wih   = (const float*)d_in[9];
    const float* Whh   = (const float*)d_in[10];
    const float* bih   = (const float*)d_in[11];
    const float* bhh   = (const float*)d_in[12];
    const float* Wout  = (const float*)d_in[13];
    const float* bout  = (const float*)d_in[14];
    float* out = (float*)d_out;

    (void)in_sizes; (void)n_in; (void)out_size;

    k_pre<<<10098, 256>>>(Wconv, bconv, Wmix, bmix, Wih, Whh, bih, bhh);
    k_scat1<<<31250, 256>>>(en, eh, ea, (const float4*)x);
    k_scat2<<<31250, 256>>>(en, eh, ea);

    cudaFuncSetAttribute(k_gru, cudaFuncAttributeMaxDynamicSharedMemorySize, SMEM_TOTAL);
    k_gru<<<148, 256, SMEM_TOTAL>>>(hprev, Wout, bout, out, NNODES);
}